// round 1
// baseline (speedup 1.0000x reference)
#include <cuda_runtime.h>
#include <cstdint>

// Shapes (fixed by the problem)
#define B 8
#define T 4096
#define D 1024
#define S 64
#define SLOT_DIM 256
#define BOND 32
#define NQ 8
#define QDIM 256
#define TCHUNK 64   // t rows per partial-sum block
#define NCHUNK (T / TCHUNK)  // 64

// ------- device scratch (no allocations allowed) -------
__device__ float g_part[B * NCHUNK * D];   // 2 MB
__device__ float g_colsum[B * D];
__device__ float g_m0[B * NQ];
__device__ float g_m1[B * NQ];
__device__ float g_overlaps[B * S];
__device__ float g_feats[S * NQ];
__device__ float g_fold[NQ * D];
__device__ float g_bias[B * D];

// ================= Kernel A1: partial column sums over t =================
// grid (NCHUNK, B), 256 threads; each thread owns 4 consecutive d via float4.
__global__ void k_partsum(const float* __restrict__ x) {
    const int c = blockIdx.x;
    const int b = blockIdx.y;
    const int tid = threadIdx.x;
    const float4* xp = reinterpret_cast<const float4*>(x) +
                       ((size_t)b * T + (size_t)c * TCHUNK) * (D / 4);
    float4 acc = make_float4(0.f, 0.f, 0.f, 0.f);
#pragma unroll 8
    for (int t = 0; t < TCHUNK; ++t) {
        float4 v = xp[t * (D / 4) + tid];
        acc.x += v.x; acc.y += v.y; acc.z += v.z; acc.w += v.w;
    }
    reinterpret_cast<float4*>(g_part)[(b * NCHUNK + c) * (D / 4) + tid] = acc;
}

// ================= Kernel A2: reduce partials -> colsum =================
// grid (B), 1024 threads
__global__ void k_colsum() {
    const int b = blockIdx.x;
    const int d = threadIdx.x;
    float acc = 0.f;
#pragma unroll 8
    for (int c = 0; c < NCHUNK; ++c)
        acc += g_part[(b * NCHUNK + c) * D + d];
    g_colsum[b * D + d] = acc;
}

// ====== Kernel B1: logits -> softmax(qa) -> amplitude means m0/m1 ======
// grid (B), 256 threads (j = output column)
__global__ void k_query(const float* __restrict__ Wq, const float* __restrict__ bq) {
    const int b = blockIdx.x;
    const int j = threadIdx.x;
    __shared__ float xs[D];
    __shared__ float qa[QDIM];
    __shared__ float red[8];

    for (int k = j; k < D; k += 256)
        xs[k] = g_colsum[b * D + k] * (1.0f / (float)T);
    __syncthreads();

    float acc = 0.f;
#pragma unroll 8
    for (int k = 0; k < D; ++k)
        acc = fmaf(xs[k], Wq[k * QDIM + j], acc);
    acc += bq[j];

    // softmax over 256
    float m = acc;
#pragma unroll
    for (int o = 16; o; o >>= 1) m = fmaxf(m, __shfl_xor_sync(0xffffffffu, m, o));
    if ((j & 31) == 0) red[j >> 5] = m;
    __syncthreads();
    float bm = red[0];
#pragma unroll
    for (int i = 1; i < 8; ++i) bm = fmaxf(bm, red[i]);
    float e = __expf(acc - bm);
    __syncthreads();
    float ssum = e;
#pragma unroll
    for (int o = 16; o; o >>= 1) ssum += __shfl_xor_sync(0xffffffffu, ssum, o);
    if ((j & 31) == 0) red[j >> 5] = ssum;
    __syncthreads();
    float tot = 0.f;
#pragma unroll
    for (int i = 0; i < 8; ++i) tot += red[i];
    qa[j] = e / tot;
    __syncthreads();

    // amplitude means with JAX OOB-clamp semantics:
    // idx = i*2s (+s for m1), i in [0, s); OOB indices clamp to 255.
    if (j < 16) {
        const int q = j & 7;
        const bool one = j >= 8;
        const int s = 1 << (7 - q);
        const int cin = min(s, 128 / s);
        float a = 0.f;
        const int off = one ? s : 0;
        for (int i = 0; i < cin; ++i) a += qa[i * 2 * s + off];
        a += (float)(s - cin) * qa[QDIM - 1];
        float* dst = one ? g_m1 : g_m0;
        dst[b * NQ + q] = a / (float)s;
    }
}

// ================= Kernel F: fold Wd rows by (c mod 8) =================
// grid (4), 256 threads
__global__ void k_fold(const float* __restrict__ Wd) {
    const int d = blockIdx.x * 256 + threadIdx.x;
    float acc[NQ];
#pragma unroll
    for (int q = 0; q < NQ; ++q) acc[q] = 0.f;
#pragma unroll 4
    for (int i = 0; i < SLOT_DIM / NQ; ++i) {
#pragma unroll
        for (int q = 0; q < NQ; ++q)
            acc[q] += Wd[(size_t)(i * NQ + q) * D + d];
    }
#pragma unroll
    for (int q = 0; q < NQ; ++q) g_fold[q * D + d] = acc[q];
}

// ====== Kernel B2: per-slot feats + MPS contraction overlaps ======
// grid (S), 256 threads = 8 warps. Warp w computes feat index w, and batch b=w overlap.
__global__ void k_slots(const float* __restrict__ cf,
                        const float* __restrict__ cm,
                        const float* __restrict__ cl) {
    const int s = blockIdx.x;
    const int tid = threadIdx.x;
    const int w = tid >> 5;
    const int lane = tid & 31;

    // ---- feats ----
    float fsum;
    float inv_cnt;
    if (w == 0) {
        fsum = cf[s * 64 + lane] + cf[s * 64 + 32 + lane];
        inv_cnt = 1.0f / 64.0f;
    } else if (w == 7) {
        fsum = cl[s * 64 + lane] + cl[s * 64 + 32 + lane];
        inv_cnt = 1.0f / 64.0f;
    } else {
        const float* base = cm + ((size_t)s * (NQ - 2) + (w - 1)) * 2048;
        fsum = 0.f;
#pragma unroll
        for (int i = 0; i < 64; ++i) fsum += base[i * 32 + lane];
        inv_cnt = 1.0f / 2048.0f;
    }
#pragma unroll
    for (int o = 16; o; o >>= 1) fsum += __shfl_xor_sync(0xffffffffu, fsum, o);
    if (lane == 0) g_feats[s * NQ + w] = fsum * inv_cnt;

    // ---- overlap for batch b = w ----
    const int b = w;
    float M0[NQ], M1[NQ];
#pragma unroll
    for (int q = 0; q < NQ; ++q) {
        M0[q] = g_m0[b * NQ + q];
        M1[q] = g_m1[b * NQ + q];
    }
    // q = 0: left bond = 1
    float v = M0[0] * cf[s * 64 + lane] + M1[0] * cf[s * 64 + 32 + lane];
    // q = 1 .. NQ-2
#pragma unroll
    for (int q = 1; q <= NQ - 2; ++q) {
        const float* base = cm + (((size_t)s * (NQ - 2) + (q - 1)) * BOND) * 64;
        float nv = 0.f;
#pragma unroll 8
        for (int l = 0; l < BOND; ++l) {
            float vl = __shfl_sync(0xffffffffu, v, l);
            float c0 = base[l * 64 + lane];
            float c1 = base[l * 64 + 32 + lane];
            nv = fmaf(vl, fmaf(M0[q], c0, M1[q] * c1), nv);
        }
        v = nv;
    }
    // q = NQ-1: right bond = 1
    float wl = M0[NQ - 1] * cl[(s * BOND + lane) * 2] +
               M1[NQ - 1] * cl[(s * BOND + lane) * 2 + 1];
    float ov = v * wl;
#pragma unroll
    for (int o = 16; o; o >>= 1) ov += __shfl_xor_sync(0xffffffffu, ov, o);
    if (lane == 0) g_overlaps[b * S + s] = ov;
}

// ====== Kernel B3: attention softmax, g = att@feats, bias = g@fold + bd ======
// grid (1), 256 threads = 8 warps; warp w handles batch b=w.
__global__ void k_readout(const float* __restrict__ bd) {
    const int tid = threadIdx.x;
    const int w = tid >> 5;
    const int lane = tid & 31;
    __shared__ float gg[B * NQ];

    float a0 = g_overlaps[w * S + lane];
    float a1 = g_overlaps[w * S + 32 + lane];
    float m = fmaxf(a0, a1);
#pragma unroll
    for (int o = 16; o; o >>= 1) m = fmaxf(m, __shfl_xor_sync(0xffffffffu, m, o));
    float e0 = __expf(a0 - m);
    float e1 = __expf(a1 - m);
    float ssum = e0 + e1;
#pragma unroll
    for (int o = 16; o; o >>= 1) ssum += __shfl_xor_sync(0xffffffffu, ssum, o);
    const float inv = 1.0f / ssum;
    const float at0 = e0 * inv;
    const float at1 = e1 * inv;

    // g[w][q] = sum_s att[w][s] * feats[s][q]
#pragma unroll
    for (int q = 0; q < NQ; ++q) {
        float p = at0 * g_feats[lane * NQ + q] + at1 * g_feats[(32 + lane) * NQ + q];
#pragma unroll
        for (int o = 16; o; o >>= 1) p += __shfl_xor_sync(0xffffffffu, p, o);
        if (lane == 0) gg[w * NQ + q] = p;
    }
    __syncthreads();

    // bias[b][d] = sum_q gg[b][q] * fold[q][d] + bd[d]
    for (int d = tid; d < D; d += 256) {
        float f[NQ];
#pragma unroll
        for (int q = 0; q < NQ; ++q) f[q] = g_fold[q * D + d];
        const float bdd = bd[d];
#pragma unroll
        for (int b = 0; b < B; ++b) {
            float acc = bdd;
#pragma unroll
            for (int q = 0; q < NQ; ++q) acc = fmaf(gg[b * NQ + q], f[q], acc);
            g_bias[b * D + d] = acc;
        }
    }
}

// ================= Kernel C: out = x + bias[b, :] broadcast =================
// grid (B*T/4), 256 threads; each block handles 4 consecutive t-rows.
__global__ void k_add(const float* __restrict__ x, float* __restrict__ out) {
    const int blk = blockIdx.x;
    const int b = blk >> 10;               // 1024 blocks per batch
    const size_t row0 = (size_t)blk * 4;
    const int tid = threadIdx.x;
    const float4 bias = reinterpret_cast<const float4*>(g_bias)[b * (D / 4) + tid];
    const float4* xp = reinterpret_cast<const float4*>(x) + row0 * (D / 4);
    float4* op = reinterpret_cast<float4*>(out) + row0 * (D / 4);
#pragma unroll
    for (int r = 0; r < 4; ++r) {
        float4 v = xp[r * (D / 4) + tid];
        v.x += bias.x; v.y += bias.y; v.z += bias.z; v.w += bias.w;
        op[r * (D / 4) + tid] = v;
    }
}

extern "C" void kernel_launch(void* const* d_in, const int* in_sizes, int n_in,
                              void* d_out, int out_size) {
    const float* x  = (const float*)d_in[0];
    const float* Wq = (const float*)d_in[1];
    const float* bq = (const float*)d_in[2];
    const float* Wd = (const float*)d_in[3];
    const float* bd = (const float*)d_in[4];
    const float* cf = (const float*)d_in[5];
    const float* cm = (const float*)d_in[6];
    const float* cl = (const float*)d_in[7];
    float* out = (float*)d_out;

    k_partsum<<<dim3(NCHUNK, B), 256>>>(x);
    k_colsum<<<B, 1024>>>();
    k_query<<<B, 256>>>(Wq, bq);
    k_fold<<<4, 256>>>(Wd);
    k_slots<<<S, 256>>>(cf, cm, cl);
    k_readout<<<1, 256>>>(bd);
    k_add<<<(B * T) / 4, 256>>>(x, out);
}

// round 2
// speedup vs baseline: 1.1906x; 1.1906x over previous
#include <cuda_runtime.h>
#include <cstdint>

#define B 8
#define T 4096
#define D 1024
#define S 64
#define SLOT_DIM 256
#define BOND 32
#define NQ 8
#define QDIM 256
#define TCHUNK 64
#define NCHUNK (T / TCHUNK)  // 64

// ------- device scratch (no allocations allowed) -------
__device__ float g_part[B * NCHUNK * D];   // 2 MB
__device__ float g_m0[B * NQ];
__device__ float g_m1[B * NQ];
__device__ float g_overlaps[B * S];
__device__ float g_feats[S * NQ];
__device__ float g_gg[B * NQ];
__device__ float g_bias[B * D];

// ================= Kernel A: partial column sums over t =================
// grid (NCHUNK, B), 256 threads; thread owns 4 consecutive d via float4.
__global__ void k_partsum(const float* __restrict__ x) {
    const int c = blockIdx.x;
    const int b = blockIdx.y;
    const int tid = threadIdx.x;
    const float4* xp = reinterpret_cast<const float4*>(x) +
                       ((size_t)b * T + (size_t)c * TCHUNK) * (D / 4);
    float4 acc = make_float4(0.f, 0.f, 0.f, 0.f);
#pragma unroll 8
    for (int t = 0; t < TCHUNK; ++t) {
        float4 v = xp[t * (D / 4) + tid];
        acc.x += v.x; acc.y += v.y; acc.z += v.z; acc.w += v.w;
    }
    reinterpret_cast<float4*>(g_part)[(b * NCHUNK + c) * (D / 4) + tid] = acc;
}

// ====== Kernel Q: reduce partials -> x_summary -> softmax(qa) -> m0/m1 ======
// grid (B), 1024 threads. j = tid&255 output col, kc = tid>>8 (4-way k split).
__global__ void k_query(const float* __restrict__ Wq, const float* __restrict__ bq) {
    const int b = blockIdx.x;
    const int tid = threadIdx.x;
    const int j = tid & 255;
    const int kc = tid >> 8;
    __shared__ float xs[D];
    __shared__ float pr[4][QDIM];
    __shared__ float qa[QDIM];
    __shared__ float red[8];

    // reduce 64 partials for d = tid
    {
        float acc = 0.f;
        const float* p = g_part + (size_t)b * NCHUNK * D + tid;
#pragma unroll 16
        for (int c = 0; c < NCHUNK; ++c) acc += p[c * D];
        xs[tid] = acc * (1.0f / (float)T);
    }
    __syncthreads();

    // GEMV: partial over k-chunk
    {
        float acc = 0.f;
        const int k0 = kc * 256;
#pragma unroll 8
        for (int k = 0; k < 256; ++k)
            acc = fmaf(xs[k0 + k], Wq[(size_t)(k0 + k) * QDIM + j], acc);
        pr[kc][j] = acc;
    }
    __syncthreads();

    float logit = 0.f;
    if (tid < QDIM)
        logit = pr[0][j] + pr[1][j] + pr[2][j] + pr[3][j] + bq[j];

    // softmax over 256 (warps 0..7 active)
    float m = logit;
#pragma unroll
    for (int o = 16; o; o >>= 1) m = fmaxf(m, __shfl_xor_sync(0xffffffffu, m, o));
    if (tid < QDIM && (tid & 31) == 0) red[tid >> 5] = m;
    __syncthreads();
    float bm = red[0];
#pragma unroll
    for (int i = 1; i < 8; ++i) bm = fmaxf(bm, red[i]);
    float e = (tid < QDIM) ? __expf(logit - bm) : 0.f;
    float ssum = e;
#pragma unroll
    for (int o = 16; o; o >>= 1) ssum += __shfl_xor_sync(0xffffffffu, ssum, o);
    __syncthreads();
    if (tid < QDIM && (tid & 31) == 0) red[tid >> 5] = ssum;
    __syncthreads();
    float tot = 0.f;
#pragma unroll
    for (int i = 0; i < 8; ++i) tot += red[i];
    if (tid < QDIM) qa[j] = e / tot;
    __syncthreads();

    // amplitude means with JAX OOB-clamp semantics (clamp to index 255)
    if (tid < 16) {
        const int q = tid & 7;
        const bool one = tid >= 8;
        const int s = 1 << (7 - q);
        const int cin = min(s, 128 / s);
        float a = 0.f;
        const int off = one ? s : 0;
        for (int i = 0; i < cin; ++i) a += qa[i * 2 * s + off];
        a += (float)(s - cin) * qa[QDIM - 1];
        float* dst = one ? g_m1 : g_m0;
        dst[b * NQ + q] = a / (float)s;
    }
}

// ====== Kernel S: per-slot feats + MPS contraction overlaps ======
// grid (S), 256 threads = 8 warps; cm slice staged in shared (48 KB).
__global__ void k_slots(const float* __restrict__ cf,
                        const float* __restrict__ cm,
                        const float* __restrict__ cl) {
    const int s = blockIdx.x;
    const int tid = threadIdx.x;
    const int w = tid >> 5;
    const int lane = tid & 31;
    __shared__ float s_cm[12288];   // 48 KB: (NQ-2)=6 levels x 32 x 64

    // cooperative load of cm slice (contiguous 12288 floats)
    {
        const float4* src = reinterpret_cast<const float4*>(cm + (size_t)s * 12288);
        float4* dst = reinterpret_cast<float4*>(s_cm);
#pragma unroll
        for (int i = 0; i < 12; ++i)
            dst[i * 256 + tid] = src[i * 256 + tid];
    }
    __syncthreads();

    // ---- feats ----
    float fsum;
    float inv_cnt;
    if (w == 0) {
        fsum = cf[s * 64 + lane] + cf[s * 64 + 32 + lane];
        inv_cnt = 1.0f / 64.0f;
    } else if (w == 7) {
        fsum = cl[s * 64 + lane] + cl[s * 64 + 32 + lane];
        inv_cnt = 1.0f / 64.0f;
    } else {
        const float* base = s_cm + (w - 1) * 2048;
        fsum = 0.f;
#pragma unroll
        for (int i = 0; i < 64; ++i) fsum += base[i * 32 + lane];
        inv_cnt = 1.0f / 2048.0f;
    }
#pragma unroll
    for (int o = 16; o; o >>= 1) fsum += __shfl_xor_sync(0xffffffffu, fsum, o);
    if (lane == 0) g_feats[s * NQ + w] = fsum * inv_cnt;

    // ---- overlap for batch b = w ----
    const int b = w;
    float M0[NQ], M1[NQ];
#pragma unroll
    for (int q = 0; q < NQ; ++q) {
        M0[q] = g_m0[b * NQ + q];
        M1[q] = g_m1[b * NQ + q];
    }
    float v = M0[0] * cf[s * 64 + lane] + M1[0] * cf[s * 64 + 32 + lane];
#pragma unroll
    for (int q = 1; q <= NQ - 2; ++q) {
        const float* base = s_cm + (q - 1) * 2048;
        float nv = 0.f;
#pragma unroll 8
        for (int l = 0; l < BOND; ++l) {
            float vl = __shfl_sync(0xffffffffu, v, l);
            float c0 = base[l * 64 + lane];
            float c1 = base[l * 64 + 32 + lane];
            nv = fmaf(vl, fmaf(M0[q], c0, M1[q] * c1), nv);
        }
        v = nv;
    }
    float wl = M0[NQ - 1] * cl[(s * BOND + lane) * 2] +
               M1[NQ - 1] * cl[(s * BOND + lane) * 2 + 1];
    float ov = v * wl;
#pragma unroll
    for (int o = 16; o; o >>= 1) ov += __shfl_xor_sync(0xffffffffu, ov, o);
    if (lane == 0) g_overlaps[b * S + s] = ov;
}

// ====== Kernel T: attention softmax + gg = att @ feats ======
// grid (1), 256 threads = 8 warps; warp w = batch b.
__global__ void k_att() {
    const int tid = threadIdx.x;
    const int w = tid >> 5;
    const int lane = tid & 31;

    float a0 = g_overlaps[w * S + lane];
    float a1 = g_overlaps[w * S + 32 + lane];
    float m = fmaxf(a0, a1);
#pragma unroll
    for (int o = 16; o; o >>= 1) m = fmaxf(m, __shfl_xor_sync(0xffffffffu, m, o));
    float e0 = __expf(a0 - m);
    float e1 = __expf(a1 - m);
    float ssum = e0 + e1;
#pragma unroll
    for (int o = 16; o; o >>= 1) ssum += __shfl_xor_sync(0xffffffffu, ssum, o);
    const float inv = 1.0f / ssum;
    const float at0 = e0 * inv;
    const float at1 = e1 * inv;

#pragma unroll
    for (int q = 0; q < NQ; ++q) {
        float p = at0 * g_feats[lane * NQ + q] + at1 * g_feats[(32 + lane) * NQ + q];
#pragma unroll
        for (int o = 16; o; o >>= 1) p += __shfl_xor_sync(0xffffffffu, p, o);
        if (lane == 0) g_gg[w * NQ + q] = p;
    }
}

// ====== Kernel W: bias[b,d] = bd[d] + sum_c gg[b, c&7] * Wd[c,d] ======
// grid (4), 256 threads; thread owns one d, 8 batch accumulators.
__global__ void k_bias(const float* __restrict__ Wd, const float* __restrict__ bd) {
    const int d = blockIdx.x * 256 + threadIdx.x;
    __shared__ float s_gg[B * NQ];
    if (threadIdx.x < B * NQ) s_gg[threadIdx.x] = g_gg[threadIdx.x];
    __syncthreads();

    float acc[B];
    const float bdd = bd[d];
#pragma unroll
    for (int b = 0; b < B; ++b) acc[b] = bdd;

#pragma unroll 4
    for (int c = 0; c < SLOT_DIM; ++c) {
        const float wv = Wd[(size_t)c * D + d];
        const int q = c & 7;
#pragma unroll
        for (int b = 0; b < B; ++b)
            acc[b] = fmaf(s_gg[b * NQ + q], wv, acc[b]);
    }
#pragma unroll
    for (int b = 0; b < B; ++b) g_bias[b * D + d] = acc[b];
}

// ================= Kernel C: out = x + bias[b, :] broadcast =================
__global__ void k_add(const float* __restrict__ x, float* __restrict__ out) {
    const int blk = blockIdx.x;
    const int b = blk >> 10;               // 1024 blocks per batch
    const size_t row0 = (size_t)blk * 4;
    const int tid = threadIdx.x;
    const float4 bias = reinterpret_cast<const float4*>(g_bias)[b * (D / 4) + tid];
    const float4* xp = reinterpret_cast<const float4*>(x) + row0 * (D / 4);
    float4* op = reinterpret_cast<float4*>(out) + row0 * (D / 4);
#pragma unroll
    for (int r = 0; r < 4; ++r) {
        float4 v = xp[r * (D / 4) + tid];
        v.x += bias.x; v.y += bias.y; v.z += bias.z; v.w += bias.w;
        op[r * (D / 4) + tid] = v;
    }
}

extern "C" void kernel_launch(void* const* d_in, const int* in_sizes, int n_in,
                              void* d_out, int out_size) {
    const float* x  = (const float*)d_in[0];
    const float* Wq = (const float*)d_in[1];
    const float* bq = (const float*)d_in[2];
    const float* Wd = (const float*)d_in[3];
    const float* bd = (const float*)d_in[4];
    const float* cf = (const float*)d_in[5];
    const float* cm = (const float*)d_in[6];
    const float* cl = (const float*)d_in[7];
    float* out = (float*)d_out;

    k_partsum<<<dim3(NCHUNK, B), 256>>>(x);
    k_query<<<B, 1024>>>(Wq, bq);
    k_slots<<<S, 256>>>(cf, cm, cl);
    k_att<<<1, 256>>>();
    k_bias<<<4, 256>>>(Wd, bd);
    k_add<<<(B * T) / 4, 256>>>(x, out);
}